// round 1
// baseline (speedup 1.0000x reference)
#include <cuda_runtime.h>
#include <math.h>

#define H 256
#define W 256
#define V 192
#define D 256
#define S 256

// ---- geometry constants (double-derived, matching numpy linspace then f32 cast) ----
#define SQRT2_D 1.4142135623730951
// sample spacing in 128-scaled (pixel) units: 128 * (2*sqrt2/255)
#define DPf    ((float)(2.0 * SQRT2_D * 128.0 / 255.0))
#define OFFf   ((float)(-SQRT2_D * 128.0))
#define INV_DPf ((float)(255.0 / (256.0 * SQRT2_D)))
#define DTf    ((float)(2.0 * SQRT2_D / 256.0))

__device__ float2 g_trig[V];          // (cos, sin) per angle
__device__ float2 g_temp[V * D];      // residual sinogram, (imgA, imgB) interleaved

// ---------------------------------------------------------------------------
// init: trig tables (double math -> f32, matching jnp.cos/sin of f32 angles)
// ---------------------------------------------------------------------------
__global__ void init_kernel() {
    int i = threadIdx.x;
    if (i < V) {
        double a  = (double)i * (3.141592653589793 / 192.0);
        float  af = (float)a;
        g_trig[i] = make_float2((float)cos((double)af), (float)sin((double)af));
    }
}

// ---------------------------------------------------------------------------
// forward projection: one warp per (v,d) ray, lanes stride over samples s.
// temp[v,d] = DT * sum_s bilerp(img, xp, yp) - proj[v,d]   (both images)
// ---------------------------------------------------------------------------
__global__ void __launch_bounds__(256) fwd_kernel(const float* __restrict__ img,
                                                  const float* __restrict__ proj) {
    const int warp = (blockIdx.x * blockDim.x + threadIdx.x) >> 5;
    const int lane = threadIdx.x & 31;
    if (warp >= V * D) return;
    const int v = warp >> 8;       // / D
    const int d = warp & 255;      // % D

    const float2 cs = g_trig[v];
    const float cv = cs.x, sv = cs.y;
    const float s128 = fmaf((float)d, DPf, OFFf);
    const float ax = fmaf(-s128, sv, 127.5f);   // xp = ax + t128*cv
    const float ay = fmaf( s128, cv, 127.5f);   // yp = ay + t128*sv

    // conservative t128-range clip to the image box (superset of nonzero samples)
    float lo = -1e30f, hi = 1e30f;
    bool empty = false;
    if (fabsf(cv) > 1e-8f) {
        float r = 1.0f / cv;
        float t1 = (-1.5f - ax) * r, t2 = (256.5f - ax) * r;
        lo = fmaxf(lo, fminf(t1, t2)); hi = fminf(hi, fmaxf(t1, t2));
    } else if (ax < -1.5f || ax > 256.5f) empty = true;
    if (fabsf(sv) > 1e-8f) {
        float r = 1.0f / sv;
        float t1 = (-1.5f - ay) * r, t2 = (256.5f - ay) * r;
        lo = fmaxf(lo, fminf(t1, t2)); hi = fminf(hi, fmaxf(t1, t2));
    } else if (ay < -1.5f || ay > 256.5f) empty = true;

    float sA = 0.f, sB = 0.f;
    if (!empty && lo <= hi) {
        int klo = max(0,     (int)floorf((lo - 2.0f - OFFf) * INV_DPf));
        int khi = min(S - 1, (int)ceilf ((hi + 2.0f - OFFf) * INV_DPf));
        const float* __restrict__ imgA = img;
        const float* __restrict__ imgB = img + H * W;
        for (int k = klo + lane; k <= khi; k += 32) {
            float t128 = fmaf((float)k, DPf, OFFf);
            float xp = fmaf(t128, cv, ax);
            float yp = fmaf(t128, sv, ay);
            int ix0 = __float2int_rd(xp);
            int iy0 = __float2int_rd(yp);
            float fx = xp - (float)ix0;
            float fy = yp - (float)iy0;
            bool vx0 = (unsigned)ix0       < (unsigned)W;
            bool vx1 = (unsigned)(ix0 + 1) < (unsigned)W;
            bool vy0 = (unsigned)iy0       < (unsigned)H;
            bool vy1 = (unsigned)(iy0 + 1) < (unsigned)H;
            int base = iy0 * W + ix0;
            float a00 = 0.f, a10 = 0.f, a01 = 0.f, a11 = 0.f;
            float b00 = 0.f, b10 = 0.f, b01 = 0.f, b11 = 0.f;
            if (vx0 && vy0) { a00 = __ldg(imgA + base);         b00 = __ldg(imgB + base); }
            if (vx1 && vy0) { a10 = __ldg(imgA + base + 1);     b10 = __ldg(imgB + base + 1); }
            if (vx0 && vy1) { a01 = __ldg(imgA + base + W);     b01 = __ldg(imgB + base + W); }
            if (vx1 && vy1) { a11 = __ldg(imgA + base + W + 1); b11 = __ldg(imgB + base + W + 1); }
            float gx = 1.f - fx, gy = 1.f - fy;
            float w00 = gx * gy, w10 = fx * gy, w01 = gx * fy, w11 = fx * fy;
            sA = fmaf(a00, w00, fmaf(a10, w10, fmaf(a01, w01, fmaf(a11, w11, sA))));
            sB = fmaf(b00, w00, fmaf(b10, w10, fmaf(b01, w01, fmaf(b11, w11, sB))));
        }
    }
    // warp reduction
    #pragma unroll
    for (int o = 16; o; o >>= 1) {
        sA += __shfl_xor_sync(0xffffffffu, sA, o);
        sB += __shfl_xor_sync(0xffffffffu, sB, o);
    }
    if (lane == 0) {
        g_temp[warp] = make_float2(fmaf(DTf, sA, -__ldg(proj + warp)),
                                   fmaf(DTf, sB, -__ldg(proj + V * D + warp)));
    }
}

// ---------------------------------------------------------------------------
// backprojection (exact adjoint, pixel-driven gather) fused with the update:
// out = img - weight * DT * sum_{v, j in {j0,j0+1}, k in {k0,k0+1}}
//              temp[v,j] * hat(dx)*hat(dy)
// No bounds checks needed: pixels inside the image always have j0,k0 in [0,254].
// ---------------------------------------------------------------------------
__global__ void __launch_bounds__(256) bwd_kernel(const float* __restrict__ img,
                                                  const float* __restrict__ wptr,
                                                  float* __restrict__ out) {
    __shared__ float2 strig[V];
    const int tid = threadIdx.x;
    for (int i = tid; i < V; i += blockDim.x) strig[i] = g_trig[i];
    __syncthreads();

    const int p = blockIdx.x * blockDim.x + tid;
    if (p >= H * W) return;
    const int ix = p & (W - 1);
    const int iy = p >> 8;
    const float px = (float)ix - 127.5f;
    const float py = (float)iy - 127.5f;
    const float npx = -px, npy = -py;

    float accA = 0.f, accB = 0.f;

    #pragma unroll 2
    for (int v = 0; v < V; ++v) {
        const float2 cs = strig[v];
        const float cv = cs.x, sv = cs.y;
        // pixel position in rotated (s,t) frame, 128-scaled units
        const float s128 = fmaf(py, cv, -px * sv);
        const float t128 = fmaf(px, cv,  py * sv);
        const float jc = fmaf(s128, INV_DPf, 127.5f);
        const float kc = fmaf(t128, INV_DPf, 127.5f);
        const float jf = floorf(jc);
        const float kf = floorf(kc);
        const int   j0 = (int)jf;
        const float u0 = fmaf(jf, DPf, OFFf), u1 = u0 + DPf;   // 128*s_det of candidates
        const float w0 = fmaf(kf, DPf, OFFf), w1 = w0 + DPf;   // 128*t of candidates
        const float nsv = -sv;
        // dx = -u*sv + w*cv - px ;  dy = u*cv + w*sv - py
        const float a0 = fmaf(u0, nsv, npx), a1 = fmaf(u1, nsv, npx);
        const float c0 = fmaf(u0, cv,  npy), c1 = fmaf(u1, cv,  npy);
        const float b0 = w0 * cv, b1 = w1 * cv;
        const float d0 = w0 * sv, d1 = w1 * sv;

        const float2 t0 = g_temp[v * D + j0];
        const float2 t1 = g_temp[v * D + j0 + 1];

        float hx, hy, ww;
        hx = fmaxf(1.f - fabsf(a0 + b0), 0.f); hy = fmaxf(1.f - fabsf(c0 + d0), 0.f);
        ww = hx * hy; accA = fmaf(t0.x, ww, accA); accB = fmaf(t0.y, ww, accB);
        hx = fmaxf(1.f - fabsf(a0 + b1), 0.f); hy = fmaxf(1.f - fabsf(c0 + d1), 0.f);
        ww = hx * hy; accA = fmaf(t0.x, ww, accA); accB = fmaf(t0.y, ww, accB);
        hx = fmaxf(1.f - fabsf(a1 + b0), 0.f); hy = fmaxf(1.f - fabsf(c1 + d0), 0.f);
        ww = hx * hy; accA = fmaf(t1.x, ww, accA); accB = fmaf(t1.y, ww, accB);
        hx = fmaxf(1.f - fabsf(a1 + b1), 0.f); hy = fmaxf(1.f - fabsf(c1 + d1), 0.f);
        ww = hx * hy; accA = fmaf(t1.x, ww, accA); accB = fmaf(t1.y, ww, accB);
    }

    const float wdt = __ldg(wptr) * DTf;
    out[p]         = fmaf(-wdt, accA, img[p]);
    out[p + H * W] = fmaf(-wdt, accB, img[p + H * W]);
}

// ---------------------------------------------------------------------------
extern "C" void kernel_launch(void* const* d_in, const int* in_sizes, int n_in,
                              void* d_out, int out_size) {
    const float* img  = (const float*)d_in[0];   // [2,1,256,256]
    const float* proj = (const float*)d_in[1];   // [2,1,192,256]
    const float* wptr = (const float*)d_in[2];   // [1]
    float* out = (float*)d_out;                  // [2,1,256,256]

    init_kernel<<<1, 256>>>();
    fwd_kernel<<<(V * D * 32) / 256, 256>>>(img, proj);
    bwd_kernel<<<(H * W) / 256, 256>>>(img, wptr, out);
}